// round 2
// baseline (speedup 1.0000x reference)
#include <cuda_runtime.h>
#include <math.h>
#include <stdint.h>

// ---------------- problem constants ----------------
constexpr int B_  = 2;
constexpr int C_  = 1024;
constexpr int H_  = 16;
constexpr int N_  = 64;
constexpr int LI_ = 4096;
constexpr int LT_ = 512;
constexpr int L_  = LI_ + LT_;   // 4608
constexpr int HID_ = 2048;

constexpr size_t XSZ   = (size_t)B_ * C_ * L_;      // 9.44M
constexpr size_t IMGSZ = (size_t)B_ * C_ * LI_;     // 8.39M
constexpr size_t TXTSZ = (size_t)B_ * C_ * LT_;     // 1.05M

// ---------------- scratch (static device memory; no allocations) -------------
__device__ float g_scond[B_ * C_];
__device__ float g_mod[2 * B_ * 6 * C_];            // [s][b][6C]
__device__ float g_x[XSZ];
__device__ float g_tmp[XSZ];
__device__ float g_r[XSZ];                          // (B,H,L,N)
__device__ float g_k[XSZ];
__device__ float g_v[XSZ];
__device__ float g_gate[XSZ];                       // silu(Wg @ mix) (B,C,L)
__device__ float g_y[XSZ];                          // scan out (B,H,L,N)
__device__ float g_z[XSZ];                          // gnorm*gate (B,C,L)
__device__ float g_attn[XSZ];
__device__ float g_img1[IMGSZ];
__device__ float g_txt1[TXTSZ];
__device__ float g_himg[IMGSZ];
__device__ float g_htxt[TXTSZ];
__device__ float g_midimg[(size_t)B_ * HID_ * LI_];
__device__ float g_midtxt[(size_t)B_ * HID_ * LT_];

// ---------------- small elementwise ----------------
__global__ void silu_cond_k(const float* __restrict__ cond, float* __restrict__ out) {
    int i = blockIdx.x * blockDim.x + threadIdx.x;
    if (i < B_ * C_) {
        float v = cond[i];
        out[i] = v / (1.f + expf(-v));
    }
}

// one warp per (stream, output-row); both batches at once
__global__ void mod_k(const float* __restrict__ Wimg, const float* __restrict__ bimg,
                      const float* __restrict__ Wtxt, const float* __restrict__ btxt,
                      const float* __restrict__ scond, float* __restrict__ modout) {
    int gw = (blockIdx.x * blockDim.x + threadIdx.x) >> 5;
    int lane = threadIdx.x & 31;
    if (gw >= 2 * 6 * C_) return;
    int s = gw / (6 * C_), o = gw % (6 * C_);
    const float* Wp = (s ? Wtxt : Wimg) + (size_t)o * C_;
    float a0 = 0.f, a1 = 0.f;
    for (int c = lane; c < C_; c += 32) {
        float wv = Wp[c];
        a0 += wv * scond[c];
        a1 += wv * scond[C_ + c];
    }
    #pragma unroll
    for (int off = 16; off; off >>= 1) {
        a0 += __shfl_down_sync(0xffffffffu, a0, off);
        a1 += __shfl_down_sync(0xffffffffu, a1, off);
    }
    if (lane == 0) {
        float bb = (s ? btxt : bimg)[o];
        modout[(s * B_ + 0) * 6 * C_ + o] = a0 + bb;
        modout[(s * B_ + 1) * 6 * C_ + o] = a1 + bb;
    }
}

// x[b,c,l] = rms(src)*(1+sc1)+sh1, concat img||txt along l. One thread per (b,l).
__global__ void buildx_k(const float* __restrict__ img, const float* __restrict__ txt,
                         const float* __restrict__ rmswi, const float* __restrict__ rmswt,
                         const float* __restrict__ mod, float* __restrict__ x) {
    int gid = blockIdx.x * blockDim.x + threadIdx.x;
    if (gid >= B_ * L_) return;
    int b = gid / L_, l = gid % L_;
    const float* src; const float* rw; int Ls, li, s;
    if (l < LI_) { src = img; Ls = LI_; li = l;       s = 0; rw = rmswi; }
    else         { src = txt; Ls = LT_; li = l - LI_; s = 1; rw = rmswt; }
    const float* sp = src + (size_t)b * C_ * Ls + li;
    float ss = 0.f;
    #pragma unroll 8
    for (int c = 0; c < C_; c++) {
        float v = sp[(size_t)c * Ls];
        ss += v * v;
    }
    float inv = rsqrtf(ss * (1.f / C_) + 1e-6f);
    const float* mb = mod + (s * B_ + b) * 6 * C_;
    float* xp = g_x == x ? x + (size_t)b * C_ * L_ + l : x + (size_t)b * C_ * L_ + l;
    #pragma unroll 8
    for (int c = 0; c < C_; c++) {
        float v = sp[(size_t)c * Ls];
        xp[(size_t)c * L_] = v * inv * rw[c] * (1.f + mb[C_ + c]) + mb[c];
    }
}

// ---------------- generic GEMM: Y[b,m,l] = epi( sum_c W[m,c]*X'[b,c,l] ) --------
// MIX: X' = (1-mu[c])*X[b,c,l] + mu[c]*X[b,c,l-1]  (l-1 within batch, 0 at l=0)
// EPI: 0 none, 1 silu, 2 gelu(tanh), 3 residual: resid + gate[b*6C+m]*acc
template <int EPI, bool MIX>
__global__ void __launch_bounds__(256)
gemm_k(const float* __restrict__ W, const float* __restrict__ X,
       float* __restrict__ Y, const float* __restrict__ mu,
       const float* __restrict__ resid, const float* __restrict__ gate,
       int M, int K, int Llen) {
    int b  = blockIdx.z;
    int m0 = blockIdx.y * 128;
    int l0 = blockIdx.x * 128;
    const float* Xb = X + (size_t)b * K * Llen;

    __shared__ float As[16][128];
    __shared__ float Bs[16][128];

    int tid = threadIdx.x;
    int tx = tid & 15, ty = tid >> 4;
    float acc[8][8] = {};

    for (int kt = 0; kt < K; kt += 16) {
        // A tile (W): 128 rows x 16 k, stored transposed As[k][m]
        #pragma unroll
        for (int i = 0; i < 2; i++) {
            int id = tid + i * 256;
            int row = id >> 2, c4 = (id & 3) * 4;
            float4 w4 = *(const float4*)(W + (size_t)(m0 + row) * K + kt + c4);
            As[c4 + 0][row] = w4.x;
            As[c4 + 1][row] = w4.y;
            As[c4 + 2][row] = w4.z;
            As[c4 + 3][row] = w4.w;
        }
        // B tile (X): 16 k x 128 l
        #pragma unroll
        for (int i = 0; i < 8; i++) {
            int id = tid + i * 256;
            int row = id >> 7, col = id & 127;
            int gl = l0 + col;
            const float* px = Xb + (size_t)(kt + row) * Llen + gl;
            float xv = *px;
            if (MIX) {
                float xp = (gl > 0) ? px[-1] : 0.f;
                float mm = mu[kt + row];
                xv += mm * (xp - xv);
            }
            Bs[row][col] = xv;
        }
        __syncthreads();
        #pragma unroll
        for (int k = 0; k < 16; k++) {
            float4 a0 = *(const float4*)&As[k][ty * 8];
            float4 a1 = *(const float4*)&As[k][ty * 8 + 4];
            float4 b0 = *(const float4*)&Bs[k][tx * 8];
            float4 b1 = *(const float4*)&Bs[k][tx * 8 + 4];
            float av[8] = {a0.x, a0.y, a0.z, a0.w, a1.x, a1.y, a1.z, a1.w};
            float bv[8] = {b0.x, b0.y, b0.z, b0.w, b1.x, b1.y, b1.z, b1.w};
            #pragma unroll
            for (int i = 0; i < 8; i++)
                #pragma unroll
                for (int j = 0; j < 8; j++)
                    acc[i][j] += av[i] * bv[j];
        }
        __syncthreads();
    }

    size_t yb = (size_t)b * M * Llen;
    #pragma unroll
    for (int i = 0; i < 8; i++) {
        int m = m0 + ty * 8 + i;
        float* yrow = Y + yb + (size_t)m * Llen + l0 + tx * 8;
        float out[8];
        #pragma unroll
        for (int j = 0; j < 8; j++) {
            float v = acc[i][j];
            if (EPI == 1) {
                v = v / (1.f + expf(-v));
            } else if (EPI == 2) {
                float t = 0.7978845608f * (v + 0.044715f * v * v * v);
                v = 0.5f * v * (1.f + tanhf(t));
            } else if (EPI == 3) {
                v = resid[yb + (size_t)m * Llen + l0 + tx * 8 + j] + gate[b * 6 * C_ + m] * v;
            }
            out[j] = v;
        }
        *(float4*)yrow       = make_float4(out[0], out[1], out[2], out[3]);
        *(float4*)(yrow + 4) = make_float4(out[4], out[5], out[6], out[7]);
    }
}

// ---------------- transpose (B,C,L) -> (B,H,L,N) ----------------
__global__ void transpose_heads_k(const float* __restrict__ in, float* __restrict__ out) {
    __shared__ float tile[32][33];
    int b = blockIdx.z;
    int c0 = blockIdx.y * 32;
    int l0 = blockIdx.x * 32;
    int tx = threadIdx.x, ty = threadIdx.y;
    #pragma unroll
    for (int i = 0; i < 32; i += 8)
        tile[ty + i][tx] = in[(size_t)b * C_ * L_ + (size_t)(c0 + ty + i) * L_ + l0 + tx];
    __syncthreads();
    int h = c0 >> 6, nb = c0 & 63;
    #pragma unroll
    for (int i = 0; i < 32; i += 8)
        out[((size_t)(b * H_ + h) * L_ + l0 + ty + i) * N_ + nb + tx] = tile[tx][ty + i];
}

// ---------------- RWKV sequential scan ----------------
// block = (bh, m-half): 256 threads = 32 m x 8 ngroups (8 n each), S in regs
__global__ void __launch_bounds__(256)
scan_k(const float* __restrict__ rr, const float* __restrict__ kk,
       const float* __restrict__ vv, const float* __restrict__ td,
       const float* __restrict__ tf, float* __restrict__ yy) {
    int bh = blockIdx.x >> 1;
    int mh = blockIdx.x & 1;
    int tid = threadIdx.x;
    int m = tid & 31;
    int ng = tid >> 5;
    int h = bh & (H_ - 1);
    size_t base = (size_t)bh * L_ * N_;

    __shared__ float sr[64], sk[64], sv[64], su[64];
    __shared__ float ps[256];
    __shared__ float sruk;

    if (tid < 64) su[tid] = tf[h * N_ + tid];
    float w[8], S[8];
    #pragma unroll
    for (int i = 0; i < 8; i++) {
        int n = ng * 8 + i;
        w[i] = expf(-expf(td[h * N_ + n]));
        S[i] = 0.f;
    }
    __syncthreads();

    int gm = mh * 32 + m;
    for (int l = 0; l < L_; l++) {
        size_t off = base + (size_t)l * N_;
        if (tid < 64)        sr[tid]       = rr[off + tid];
        else if (tid < 128)  sk[tid - 64]  = kk[off + tid - 64];
        else if (tid < 192)  sv[tid - 128] = vv[off + tid - 128];
        __syncthreads();

        if (tid < 32) {  // warp0: ruk = sum_n r*u*k
            float p = sr[tid] * su[tid] * sk[tid] + sr[tid + 32] * su[tid + 32] * sk[tid + 32];
            #pragma unroll
            for (int o = 16; o; o >>= 1) p += __shfl_down_sync(0xffffffffu, p, o);
            if (tid == 0) sruk = p;
        }

        float vm = sv[gm];
        float4 r0 = *(const float4*)&sr[ng * 8];
        float4 r1 = *(const float4*)&sr[ng * 8 + 4];
        float4 k0 = *(const float4*)&sk[ng * 8];
        float4 k1 = *(const float4*)&sk[ng * 8 + 4];
        float rv[8] = {r0.x, r0.y, r0.z, r0.w, r1.x, r1.y, r1.z, r1.w};
        float kv[8] = {k0.x, k0.y, k0.z, k0.w, k1.x, k1.y, k1.z, k1.w};

        float partial = 0.f;
        #pragma unroll
        for (int i = 0; i < 8; i++) {
            partial += rv[i] * S[i];
            S[i] = w[i] * S[i] + kv[i] * vm;
        }
        ps[tid] = partial;
        __syncthreads();

        if (tid < 32) {
            float y = sruk * vm;
            #pragma unroll
            for (int j = 0; j < 8; j++) y += ps[m + 32 * j];
            yy[off + gm] = y;
        }
        __syncthreads();
    }
}

// ---------------- groupnorm(y over N) * ln_x * gate, transpose to (B,C,L) ------
__global__ void __launch_bounds__(256)
gnorm_k(const float* __restrict__ yy, const float* __restrict__ gate,
        const float* __restrict__ lnw, const float* __restrict__ lnb,
        float* __restrict__ z) {
    int b = blockIdx.z, h = blockIdx.y, l0 = blockIdx.x * 64;
    __shared__ float tile[64][65];          // [n][l]
    __shared__ float rs1[4][64], rs2[4][64];
    __shared__ float smean[64], sinv[64];
    int tid = threadIdx.x;
    size_t ybase = ((size_t)(b * H_ + h) * L_ + l0) * N_;

    #pragma unroll
    for (int i = 0; i < 16; i++) {
        int id = tid + i * 256;
        int row = id >> 6;   // l
        int col = id & 63;   // n
        tile[col][row] = yy[ybase + (size_t)row * N_ + col];
    }
    __syncthreads();
    {
        int l = tid & 63, part = tid >> 6;
        float s1 = 0.f, s2 = 0.f;
        #pragma unroll
        for (int i = 0; i < 16; i++) {
            float v = tile[part * 16 + i][l];
            s1 += v; s2 += v * v;
        }
        rs1[part][l] = s1; rs2[part][l] = s2;
    }
    __syncthreads();
    if (tid < 64) {
        float s1 = rs1[0][tid] + rs1[1][tid] + rs1[2][tid] + rs1[3][tid];
        float s2 = rs2[0][tid] + rs2[1][tid] + rs2[2][tid] + rs2[3][tid];
        float mean = s1 * (1.f / 64);
        float var = s2 * (1.f / 64) - mean * mean;
        smean[tid] = mean;
        sinv[tid] = rsqrtf(var + 1e-5f);
    }
    __syncthreads();

    int n = tid >> 2, lq = tid & 3;
    int c = h * 64 + n;
    float lw = lnw[c], lb = lnb[c];
    size_t zofs = (size_t)b * C_ * L_ + (size_t)c * L_ + l0 + lq * 16;
    const float* gp = gate + zofs;
    float* zp = z + zofs;
    #pragma unroll
    for (int q = 0; q < 16; q += 4) {
        float4 o;
        float* po = &o.x;
        #pragma unroll
        for (int e = 0; e < 4; e++) {
            int l = lq * 16 + q + e;
            float v = (tile[n][l] - smean[l]) * sinv[l] * lw + lb;
            po[e] = v * gp[q + e];
        }
        *(float4*)(zp + q) = o;
    }
}

// ---------------- attn residual + rms for FFN input ----------------
__global__ void resid_rms_k(const float* __restrict__ img, const float* __restrict__ txt,
                            const float* __restrict__ attn, const float* __restrict__ mod,
                            const float* __restrict__ w2i, const float* __restrict__ w2t,
                            float* __restrict__ img1, float* __restrict__ txt1,
                            float* __restrict__ himg, float* __restrict__ htxt) {
    int gid = blockIdx.x * blockDim.x + threadIdx.x;
    if (gid >= B_ * L_) return;
    int b = gid / L_, l = gid % L_;
    int s, li, Ls;
    const float* src; float* d1; float* dh; const float* rw;
    if (l < LI_) { s = 0; li = l;       Ls = LI_; src = img; d1 = img1; dh = himg; rw = w2i; }
    else         { s = 1; li = l - LI_; Ls = LT_; src = txt; d1 = txt1; dh = htxt; rw = w2t; }
    const float* mb = mod + (s * B_ + b) * 6 * C_;
    const float* ap = attn + (size_t)b * C_ * L_ + l;
    const float* sp = src + (size_t)b * C_ * Ls + li;
    float* p1 = d1 + (size_t)b * C_ * Ls + li;
    float* ph = dh + (size_t)b * C_ * Ls + li;
    float ss = 0.f;
    #pragma unroll 8
    for (int c = 0; c < C_; c++) {
        float v = sp[(size_t)c * Ls] + mb[2 * C_ + c] * ap[(size_t)c * L_];
        p1[(size_t)c * Ls] = v;
        ss += v * v;
    }
    float inv = rsqrtf(ss * (1.f / C_) + 1e-6f);
    #pragma unroll 8
    for (int c = 0; c < C_; c++) {
        float v = p1[(size_t)c * Ls];
        ph[(size_t)c * Ls] = v * inv * rw[c] * (1.f + mb[4 * C_ + c]) + mb[3 * C_ + c];
    }
}

// ---------------- host launcher ----------------
static float* symaddr(const void* s) {
    void* p = nullptr;
    cudaGetSymbolAddress(&p, s);
    return (float*)p;
}

extern "C" void kernel_launch(void* const* d_in, const int* in_sizes, int n_in,
                              void* d_out, int out_size) {
    const float* img   = (const float*)d_in[0];
    const float* txt   = (const float*)d_in[1];
    const float* cond  = (const float*)d_in[2];
    const float* Wmi   = (const float*)d_in[3];
    const float* bmi   = (const float*)d_in[4];
    const float* Wmt   = (const float*)d_in[5];
    const float* bmt   = (const float*)d_in[6];
    const float* rmsi  = (const float*)d_in[7];
    const float* rmst  = (const float*)d_in[8];
    const float* rmsi2 = (const float*)d_in[9];
    const float* rmst2 = (const float*)d_in[10];
    const float* mur   = (const float*)d_in[11];
    const float* muk   = (const float*)d_in[12];
    const float* muv   = (const float*)d_in[13];
    const float* mug   = (const float*)d_in[14];
    const float* Wr    = (const float*)d_in[15];
    const float* Wk    = (const float*)d_in[16];
    const float* Wv    = (const float*)d_in[17];
    const float* Wg    = (const float*)d_in[18];
    const float* Wo    = (const float*)d_in[19];
    const float* td    = (const float*)d_in[20];
    const float* tf    = (const float*)d_in[21];
    const float* lnw   = (const float*)d_in[22];
    const float* lnb   = (const float*)d_in[23];
    const float* fi1   = (const float*)d_in[24];
    const float* fi2   = (const float*)d_in[25];
    const float* ft1   = (const float*)d_in[26];
    const float* ft2   = (const float*)d_in[27];

    float* p_scond = symaddr(g_scond);
    float* p_mod   = symaddr(g_mod);
    float* p_x     = symaddr(g_x);
    float* p_tmp   = symaddr(g_tmp);
    float* p_r     = symaddr(g_r);
    float* p_k     = symaddr(g_k);
    float* p_v     = symaddr(g_v);
    float* p_gate  = symaddr(g_gate);
    float* p_y     = symaddr(g_y);
    float* p_z     = symaddr(g_z);
    float* p_attn  = symaddr(g_attn);
    float* p_img1  = symaddr(g_img1);
    float* p_txt1  = symaddr(g_txt1);
    float* p_himg  = symaddr(g_himg);
    float* p_htxt  = symaddr(g_htxt);
    float* p_mi    = symaddr(g_midimg);
    float* p_mt    = symaddr(g_midtxt);

    float* out_img = (float*)d_out;
    float* out_txt = out_img + IMGSZ;

    // 1) silu(cond), modulation vectors
    silu_cond_k<<<(B_ * C_ + 255) / 256, 256>>>(cond, p_scond);
    mod_k<<<(2 * 6 * C_) / 8, 256>>>(Wmi, bmi, Wmt, bmt, p_scond, p_mod);

    // 2) x = concat(rms-mod img, rms-mod txt)
    buildx_k<<<(B_ * L_) / 256, 256>>>(img, txt, rmsi, rmst, p_mod, p_x);

    dim3 gFull(L_ / 128, C_ / 128, B_);
    dim3 gTr(L_ / 32, C_ / 32, B_);

    // 3) r,k,v with time-mix fused; transpose to heads
    gemm_k<0, true><<<gFull, 256>>>(Wr, p_x, p_tmp, mur, nullptr, nullptr, C_, C_, L_);
    transpose_heads_k<<<gTr, dim3(32, 8)>>>(p_tmp, p_r);
    gemm_k<0, true><<<gFull, 256>>>(Wk, p_x, p_tmp, muk, nullptr, nullptr, C_, C_, L_);
    transpose_heads_k<<<gTr, dim3(32, 8)>>>(p_tmp, p_k);
    gemm_k<0, true><<<gFull, 256>>>(Wv, p_x, p_tmp, muv, nullptr, nullptr, C_, C_, L_);
    transpose_heads_k<<<gTr, dim3(32, 8)>>>(p_tmp, p_v);
    // g = silu(Wg @ mix)
    gemm_k<1, true><<<gFull, 256>>>(Wg, p_x, p_gate, mug, nullptr, nullptr, C_, C_, L_);

    // 4) sequential RWKV scan
    scan_k<<<B_ * H_ * 2, 256>>>(p_r, p_k, p_v, td, tf, p_y);

    // 5) groupnorm + ln_x + gate, back to (B,C,L)
    gnorm_k<<<dim3(L_ / 64, H_, B_), 256>>>(p_y, p_gate, lnw, lnb, p_z);

    // 6) attn = Wo @ z
    gemm_k<0, false><<<gFull, 256>>>(Wo, p_z, p_attn, nullptr, nullptr, nullptr, C_, C_, L_);

    // 7) residual + rms for FFN input
    resid_rms_k<<<(B_ * L_) / 256, 256>>>(img, txt, p_attn, p_mod, rmsi2, rmst2,
                                          p_img1, p_txt1, p_himg, p_htxt);

    // 8) FFN img
    gemm_k<2, false><<<dim3(LI_ / 128, HID_ / 128, B_), 256>>>(
        fi1, p_himg, p_mi, nullptr, nullptr, nullptr, HID_, C_, LI_);
    gemm_k<3, false><<<dim3(LI_ / 128, C_ / 128, B_), 256>>>(
        fi2, p_mi, out_img, nullptr, p_img1, p_mod + 0 * B_ * 6 * C_ + 5 * C_, C_, HID_, LI_);

    // 9) FFN txt
    gemm_k<2, false><<<dim3(LT_ / 128, HID_ / 128, B_), 256>>>(
        ft1, p_htxt, p_mt, nullptr, nullptr, nullptr, HID_, C_, LT_);
    gemm_k<3, false><<<dim3(LT_ / 128, C_ / 128, B_), 256>>>(
        ft2, p_mt, out_txt, nullptr, p_txt1, p_mod + 1 * B_ * 6 * C_ + 5 * C_, C_, HID_, LT_);
}